// round 14
// baseline (speedup 1.0000x reference)
#include <cuda_runtime.h>
#include <cuda_bf16.h>

typedef unsigned long long ull;

// Zero-padded transform-domain input: [s 4][g1p 34][g2p 34][tile 256][uv 16]
// Borders (g1p=0,33 / g2p=0,33) are never written -> stay zero (static init).
__device__ float g_T[18939904];
// Weight pairs over uv: g_wp2[((ds*9+tap)*8 + uvp)*2 + br] = (U[2uvp], U[2uvp+1])
__device__ ull g_wp2[1296];

__device__ __forceinline__ ull pack2(float x, float y) {
    ull r; asm("mov.b64 %0, {%1, %2};" : "=l"(r) : "f"(x), "f"(y)); return r;
}
__device__ __forceinline__ ull fma2(ull a, ull b, ull c) {
    ull d; asm("fma.rn.f32x2 %0, %1, %2, %3;" : "=l"(d) : "l"(a), "l"(b), "l"(c)); return d;
}
__device__ __forceinline__ float sigm(float v) { return 1.0f / (1.0f + __expf(-v)); }

// ---------------------------------------------------------------------------
// Kernel 1: global input transform (+ weight prep in the extra block).
// ---------------------------------------------------------------------------
__global__ __launch_bounds__(256)
void xform_kernel(const float* __restrict__ x, const float* __restrict__ kern) {
    if (blockIdx.x == 4096) {
        int i = threadIdx.x;
        if (i >= 162) return;
        int br = i / 81;
        int r  = i % 81;
        int ds = r / 9, tap = r % 9;
        int ds1 = ds / 3, ds2 = ds % 3;
        int dh1 = tap / 3, dw1 = tap % 3;
        float g[3][3];
        for (int a = 0; a < 3; a++)
            for (int b = 0; b < 3; b++) {
                int idx = (br == 0)
                    ? (((((ds1*3+ds2)*3+dh1)*3+dw1)*3+a)*3+b)
                    : (((((ds2*3+ds1)*3+a)*3+b)*3+dh1)*3+dw1);
                g[a][b] = kern[idx];
            }
        float t[4][3];
        for (int c = 0; c < 3; c++) {
            t[0][c] = g[0][c];
            t[1][c] = 0.5f*(g[0][c]+g[1][c]+g[2][c]);
            t[2][c] = 0.5f*(g[0][c]-g[1][c]+g[2][c]);
            t[3][c] = g[2][c];
        }
        for (int u = 0; u < 4; u++) {
            float U[4];
            U[0] = t[u][0];
            U[1] = 0.5f*(t[u][0]+t[u][1]+t[u][2]);
            U[2] = 0.5f*(t[u][0]-t[u][1]+t[u][2]);
            U[3] = t[u][2];
            for (int vp = 0; vp < 2; vp++) {
                int uvp = u*2 + vp;
                g_wp2[((ds*9+tap)*8 + uvp)*2 + br] = pack2(U[2*vp], U[2*vp+1]);
            }
        }
        return;
    }
    int gid = blockIdx.x * 256 + threadIdx.x;     // 0 .. 1048575
    int tt = gid & 255;
    int ti = tt >> 4, tj = tt & 15;
    int pg = gid >> 8;                            // s*1024 + g1*32 + g2
    int g2 = pg & 31, g1 = (pg >> 5) & 31, s = pg >> 10;
    const float* xs = x + pg * 1024;
    int h0 = 2*ti - 1, w0 = 2*tj - 1;
    float d[4][4];
#pragma unroll
    for (int r = 0; r < 4; r++) {
#pragma unroll
        for (int c = 0; c < 4; c++) {
            int h = h0 + r, w = w0 + c;
            float v = 0.0f;
            if (((unsigned)h < 32u) && ((unsigned)w < 32u))
                v = fmaxf(xs[h*32 + w], 0.0f);
            d[r][c] = v;
        }
    }
    float tr[4][4];
#pragma unroll
    for (int c = 0; c < 4; c++) {
        tr[0][c] = d[0][c] - d[2][c];
        tr[1][c] = d[1][c] + d[2][c];
        tr[2][c] = d[2][c] - d[1][c];
        tr[3][c] = d[1][c] - d[3][c];
    }
    float* o = g_T + ((((long)s*34 + (g1+1))*34 + (g2+1))*256 + tt)*16;
#pragma unroll
    for (int u = 0; u < 4; u++) {
        float V0 = tr[u][0] - tr[u][2];
        float V1 = tr[u][1] + tr[u][2];
        float V2 = tr[u][2] - tr[u][1];
        float V3 = tr[u][1] - tr[u][3];
        *(float4*)(o + u*4) = make_float4(V0, V1, V2, V3);
    }
}

// ---------------------------------------------------------------------------
// Kernel 2: transform-domain accumulate + inverse + sigmoid/mask/sum.
// CTA: (h1,w1) 4x4 region x 4x4 tile-block (8x8 h2w2) = 1024 outputs.
// 128 threads = tile-local tl(16) x uvp(8). 8 phases of (h1, w1-half).
// Per (dh1): dedup'd 4-g2 T loads per s, double-buffered across s (MLP 8).
// SMEM: Wsm 1296 ull (10368 B) + M [16][136] fl (8704 B) = 19072 B.
// ---------------------------------------------------------------------------
#define SMEM_BYTES 19072
#define TS_S   4734976L   // 34*34*4096 floats
#define TS_G1  139264L    // 34*4096
#define TS_G2  4096L      // 256*16

__global__ __launch_bounds__(128, 6)
void conv_kernel(const float* __restrict__ x, float* __restrict__ out) {
    extern __shared__ float sm[];
    ull* Wsm = (ull*)sm;
    float* M = sm + 2592;

    const int tid = threadIdx.x;
    const int bid = blockIdx.x;
    const int B2  = bid & 3;
    const int B1  = (bid >> 2) & 3;
    const int bw1 = (bid >> 4) & 7;
    const int bh1 = bid >> 7;

    for (int i = tid; i < 1296; i += 128) Wsm[i] = g_wp2[i];

    const int uvp = tid & 7;
    const int tl  = tid >> 3;
    const int ta  = tl >> 2, tb = tl & 3;
    const long toff = (((B1*4 + ta)*16 + (B2*4 + tb))*16) + 2*uvp;
    const ulonglong2* Wq = (const ulonglong2*)Wsm;
    __syncthreads();

// consume one (dh1, s): 12 LDS.128 weights + 48 fma2, tv register-selected
#define CONSUME(S1I, S2I, TV)                                                   \
    do {                                                                        \
        _Pragma("unroll")                                                       \
        for (int dw1 = 0; dw1 < 3; dw1++) {                                     \
            const int tap8 = (dh1*3 + dw1) * 8;                                 \
            ulonglong2 w0 = Wq[uvp + (((S1I)+1)*3 + (S2I)+1)*72 + tap8];        \
            ulonglong2 w1 = Wq[uvp + (((S1I)+1)*3 + (S2I)  )*72 + tap8];        \
            ulonglong2 w2 = Wq[uvp + (((S1I)  )*3 + (S2I)+1)*72 + tap8];        \
            ulonglong2 w3 = Wq[uvp + (((S1I)  )*3 + (S2I)  )*72 + tap8];        \
            _Pragma("unroll")                                                   \
            for (int wl = 0; wl < 2; wl++) {                                    \
                ull tvv = (TV)[dw1 + wl];                                       \
                acc[wl][0][0] = fma2(tvv, w0.x, acc[wl][0][0]);                 \
                acc[wl][0][1] = fma2(tvv, w0.y, acc[wl][0][1]);                 \
                acc[wl][1][0] = fma2(tvv, w1.x, acc[wl][1][0]);                 \
                acc[wl][1][1] = fma2(tvv, w1.y, acc[wl][1][1]);                 \
                acc[wl][2][0] = fma2(tvv, w2.x, acc[wl][2][0]);                 \
                acc[wl][2][1] = fma2(tvv, w2.y, acc[wl][2][1]);                 \
                acc[wl][3][0] = fma2(tvv, w3.x, acc[wl][3][0]);                 \
                acc[wl][3][1] = fma2(tvv, w3.y, acc[wl][3][1]);                 \
            }                                                                   \
        }                                                                       \
    } while (0)

#define LOADTV(TV, TB)                                                          \
    do {                                                                        \
        const float* _p = (TB) + dh1*TS_G1;                                     \
        (TV)[0] = *(const ull*)(_p);                                            \
        (TV)[1] = *(const ull*)(_p + TS_G2);                                    \
        (TV)[2] = *(const ull*)(_p + 2*TS_G2);                                  \
        (TV)[3] = *(const ull*)(_p + 3*TS_G2);                                  \
    } while (0)

#pragma unroll 1
    for (int qb = 0; qb < 8; qb++) {
        const int h1  = qb >> 1;
        const int w1h = qb & 1;
        const int H1  = bh1*4 + h1;
        const int g2p0 = bw1*4 + w1h*2;      // padded g2 base

        const float* Tb0 = g_T + ((0*34 + H1)*34 + g2p0)*TS_G2 + toff;
        const float* Tb1 = Tb0 + TS_S;
        const float* Tb2 = Tb1 + TS_S;
        const float* Tb3 = Tb2 + TS_S;

        ull acc[2][4][2];
#pragma unroll
        for (int wl = 0; wl < 2; wl++)
#pragma unroll
            for (int so = 0; so < 4; so++) { acc[wl][so][0] = 0ull; acc[wl][so][1] = 0ull; }

#pragma unroll
        for (int dh1 = 0; dh1 < 3; dh1++) {
            ull tva[4], tvb[4];
            LOADTV(tva, Tb0);          // s=0 in flight
            LOADTV(tvb, Tb1);          // s=1 in flight
            CONSUME(0, 0, tva);        // s=0
            LOADTV(tva, Tb2);          // s=2 in flight
            CONSUME(0, 1, tvb);        // s=1
            LOADTV(tvb, Tb3);          // s=3 in flight
            CONSUME(1, 0, tva);        // s=2
            CONSUME(1, 1, tvb);        // s=3
        }

        // ---- per-wl epilogue: write M half, inverse+sigmoid+mask+reduce ----
#pragma unroll 1
        for (int wl = 0; wl < 2; wl++) {
            __syncthreads();   // prior epilogue read done / acc ready
#pragma unroll
            for (int so = 0; so < 4; so++)
#pragma unroll
                for (int br = 0; br < 2; br++)
                    *(ull*)(M + tl*136 + (so*2 + br)*16 + 2*uvp) = acc[wl][so][br];
            __syncthreads();

            if (tid < 64) {
                const int so = tid & 3;
                const int t  = tid >> 2;
                const int W1 = bw1*4 + w1h*2 + wl;
                const int ti = B1*4 + (t >> 2);
                const int tj = B2*4 + (t & 3);
                const float* mc = M + t*136 + so*32;

                float p[4] = {0.f, 0.f, 0.f, 0.f};
#pragma unroll
                for (int br = 0; br < 2; br++) {
                    float m[16];
#pragma unroll
                    for (int u = 0; u < 16; u += 4) {
                        float4 mv = *(const float4*)(mc + br*16 + u);
                        m[u] = mv.x; m[u+1] = mv.y; m[u+2] = mv.z; m[u+3] = mv.w;
                    }
                    float p0[4], p1[4];
#pragma unroll
                    for (int c = 0; c < 4; c++) {
                        p0[c] = m[c] + m[4+c] + m[8+c];
                        p1[c] = m[4+c] - m[8+c] - m[12+c];
                    }
                    p[0] += sigm(p0[0] + p0[1] + p0[2]);
                    p[1] += sigm(p0[1] - p0[2] - p0[3]);
                    p[2] += sigm(p1[0] + p1[1] + p1[2]);
                    p[3] += sigm(p1[1] - p1[2] - p1[3]);
                }
                const float* xs = x + so*1048576 + (H1*32 + W1)*1024 + (2*ti)*32 + 2*tj;
                float2 x0 = *(const float2*)xs;
                float2 x1 = *(const float2*)(xs + 32);
                p[0] = (x0.x != 0.0f) ? p[0] : 0.0f;
                p[1] = (x0.y != 0.0f) ? p[1] : 0.0f;
                p[2] = (x1.x != 0.0f) ? p[2] : 0.0f;
                p[3] = (x1.y != 0.0f) ? p[3] : 0.0f;
#pragma unroll
                for (int k = 0; k < 4; k++) {
                    p[k] += __shfl_xor_sync(0xFFFFFFFFu, p[k], 1);
                    p[k] += __shfl_xor_sync(0xFFFFFFFFu, p[k], 2);
                }
                if (so == 0) {
                    float* op = out + (H1*32 + W1)*1024 + (2*ti)*32 + 2*tj;
                    *(float2*)op        = make_float2(p[0], p[1]);
                    *(float2*)(op + 32) = make_float2(p[2], p[3]);
                }
            }
        }
    }
#undef CONSUME
#undef LOADTV
}

extern "C" void kernel_launch(void* const* d_in, const int* in_sizes, int n_in,
                              void* d_out, int out_size) {
    const float* x    = (const float*)d_in[0];   // (1,2,2,32,32,32,32)
    const float* kern = (const float*)d_in[1];   // (729,)
    float* out = (float*)d_out;                  // (1,32,32,32,32)

    xform_kernel<<<4097, 256>>>(x, kern);
    conv_kernel<<<1024, 128, SMEM_BYTES>>>(x, out);
}

// round 15
// speedup vs baseline: 3.0146x; 3.0146x over previous
#include <cuda_runtime.h>
#include <cuda_bf16.h>

typedef unsigned long long ull;

// Zero-padded transform-domain input: [s 4][g1p 34][g2p 34][tile 256][uv 16]
// Borders (g1p=0,33 / g2p=0,33) are never written -> stay zero (static init).
__device__ float g_T[18939904];
// Weight pairs over uv: g_wp2[((ds*9+tap)*8 + uvp)*2 + br] = (U[2uvp], U[2uvp+1])
__device__ ull g_wp2[1296];

__device__ __forceinline__ ull pack2(float x, float y) {
    ull r; asm("mov.b64 %0, {%1, %2};" : "=l"(r) : "f"(x), "f"(y)); return r;
}
__device__ __forceinline__ ull fma2(ull a, ull b, ull c) {
    ull d; asm("fma.rn.f32x2 %0, %1, %2, %3;" : "=l"(d) : "l"(a), "l"(b), "l"(c)); return d;
}
__device__ __forceinline__ float sigm(float v) { return 1.0f / (1.0f + __expf(-v)); }

// ---------------------------------------------------------------------------
// Kernel 1: global input transform (+ weight prep in the extra block).
// ---------------------------------------------------------------------------
__global__ __launch_bounds__(256)
void xform_kernel(const float* __restrict__ x, const float* __restrict__ kern) {
    if (blockIdx.x == 4096) {
        // ---- weight prep: U = G g G^T per (branch, ds, tap) ----
        int i = threadIdx.x;
        if (i >= 162) return;
        int br = i / 81;
        int r  = i % 81;
        int ds = r / 9, tap = r % 9;
        int ds1 = ds / 3, ds2 = ds % 3;
        int dh1 = tap / 3, dw1 = tap % 3;
        float g[3][3];
        for (int a = 0; a < 3; a++)
            for (int b = 0; b < 3; b++) {
                int idx = (br == 0)
                    ? (((((ds1*3+ds2)*3+dh1)*3+dw1)*3+a)*3+b)
                    : (((((ds2*3+ds1)*3+a)*3+b)*3+dh1)*3+dw1);
                g[a][b] = kern[idx];
            }
        float t[4][3];
        for (int c = 0; c < 3; c++) {
            t[0][c] = g[0][c];
            t[1][c] = 0.5f*(g[0][c]+g[1][c]+g[2][c]);
            t[2][c] = 0.5f*(g[0][c]-g[1][c]+g[2][c]);
            t[3][c] = g[2][c];
        }
        for (int u = 0; u < 4; u++) {
            float U[4];
            U[0] = t[u][0];
            U[1] = 0.5f*(t[u][0]+t[u][1]+t[u][2]);
            U[2] = 0.5f*(t[u][0]-t[u][1]+t[u][2]);
            U[3] = t[u][2];
            for (int vp = 0; vp < 2; vp++) {
                int uvp = u*2 + vp;
                g_wp2[((ds*9+tap)*8 + uvp)*2 + br] = pack2(U[2*vp], U[2*vp+1]);
            }
        }
        return;
    }
    int gid = blockIdx.x * 256 + threadIdx.x;     // 0 .. 1048575
    int tt = gid & 255;
    int ti = tt >> 4, tj = tt & 15;
    int pg = gid >> 8;                            // s*1024 + g1*32 + g2
    int g2 = pg & 31, g1 = (pg >> 5) & 31, s = pg >> 10;
    const float* xs = x + pg * 1024;
    int h0 = 2*ti - 1, w0 = 2*tj - 1;
    float d[4][4];
#pragma unroll
    for (int r = 0; r < 4; r++) {
#pragma unroll
        for (int c = 0; c < 4; c++) {
            int h = h0 + r, w = w0 + c;
            float v = 0.0f;
            if (((unsigned)h < 32u) && ((unsigned)w < 32u))
                v = fmaxf(xs[h*32 + w], 0.0f);
            d[r][c] = v;
        }
    }
    float tr[4][4];
#pragma unroll
    for (int c = 0; c < 4; c++) {
        tr[0][c] = d[0][c] - d[2][c];
        tr[1][c] = d[1][c] + d[2][c];
        tr[2][c] = d[2][c] - d[1][c];
        tr[3][c] = d[1][c] - d[3][c];
    }
    float* o = g_T + ((((long)s*34 + (g1+1))*34 + (g2+1))*256 + tt)*16;
#pragma unroll
    for (int u = 0; u < 4; u++) {
        float V0 = tr[u][0] - tr[u][2];
        float V1 = tr[u][1] + tr[u][2];
        float V2 = tr[u][2] - tr[u][1];
        float V3 = tr[u][1] - tr[u][3];
        *(float4*)(o + u*4) = make_float4(V0, V1, V2, V3);
    }
}

// ---------------------------------------------------------------------------
// Kernel 2 (R12-proven hot loop): transform-domain accumulate + epilogue.
// CTA: (h1,w1) 4x4 region x 4x4 tile-block (8x8 h2w2) = 1024 outputs.
// 128 threads = tile-local tl(16) x uvp(8). 8 phases of (h1, w1-half).
// Tap-outer loop: 8 unconditional T-LDG.64 per tap (compiler-batched MLP),
// then per-s weights via immediate-offset LDS.128 and 16 fma2.
// SMEM: Wsm 1296 ull (10368 B) + M [2][16][136] fl (17408 B) = 27776 B.
// ---------------------------------------------------------------------------
#define SMEM_BYTES 27776
#define TS_S   4734976L   // 34*34*4096 floats
#define TS_G1  139264L    // 34*4096
#define TS_G2  4096L      // 256*16

__global__ __launch_bounds__(128, 6)
void conv_kernel(const float* __restrict__ x, float* __restrict__ out) {
    extern __shared__ float sm[];
    ull* Wsm = (ull*)sm;
    float* M = sm + 2592;

    const int tid = threadIdx.x;
    const int bid = blockIdx.x;
    const int B2  = bid & 3;
    const int B1  = (bid >> 2) & 3;
    const int bw1 = (bid >> 4) & 7;
    const int bh1 = bid >> 7;

    {   // vectorized weight copy (648 x 16B)
        ulonglong2* Wd = (ulonglong2*)Wsm;
        const ulonglong2* Ws = (const ulonglong2*)g_wp2;
        for (int i = tid; i < 648; i += 128) Wd[i] = Ws[i];
    }

    const int uvp = tid & 7;
    const int tl  = tid >> 3;
    const int ta  = tl >> 2, tb = tl & 3;
    const long toff = (((B1*4 + ta)*16 + (B2*4 + tb))*16) + 2*uvp;
    const ulonglong2* Wq = (const ulonglong2*)Wsm;
    __syncthreads();

#pragma unroll 1
    for (int qb = 0; qb < 8; qb++) {
        const int h1  = qb >> 1;
        const int w1h = qb & 1;
        const int H1  = bh1*4 + h1;
        const int g2p0 = bw1*4 + w1h*2;      // padded g2 base

        // Per-s_in T base pointers (padded layout: no bounds checks anywhere)
        const float* Tb0 = g_T + ((0*34 + H1)*34 + g2p0)*TS_G2 + toff;
        const float* Tb1 = Tb0 + TS_S;
        const float* Tb2 = Tb1 + TS_S;
        const float* Tb3 = Tb2 + TS_S;

        ull acc[2][4][2];
#pragma unroll
        for (int wl = 0; wl < 2; wl++)
#pragma unroll
            for (int so = 0; so < 4; so++) { acc[wl][so][0] = 0ull; acc[wl][so][1] = 0ull; }

#pragma unroll
        for (int dh1 = 0; dh1 < 3; dh1++) {
#pragma unroll
            for (int dw1 = 0; dw1 < 3; dw1++) {
                // ---- 8 independent T loads (immediate offsets) ----
                ull tv[4][2];
#pragma unroll
                for (int wl = 0; wl < 2; wl++) {
                    const long o = dh1*TS_G1 + (dw1+wl)*TS_G2;
                    tv[0][wl] = *(const ull*)(Tb0 + o);
                    tv[1][wl] = *(const ull*)(Tb1 + o);
                    tv[2][wl] = *(const ull*)(Tb2 + o);
                    tv[3][wl] = *(const ull*)(Tb3 + o);
                }
                const int tap8 = (dh1*3 + dw1) * 8;
#pragma unroll
                for (int s = 0; s < 4; s++) {
                    const int s1i = s >> 1, s2i = s & 1;
                    // ds(s,so)*72 folds to a compile-time constant per (s,so)
                    ulonglong2 w0 = Wq[uvp + ((s1i+1)*3 + s2i+1)*72 + tap8];
                    ulonglong2 w1 = Wq[uvp + ((s1i+1)*3 + s2i  )*72 + tap8];
                    ulonglong2 w2 = Wq[uvp + (( s1i )*3 + s2i+1)*72 + tap8];
                    ulonglong2 w3 = Wq[uvp + (( s1i )*3 + s2i  )*72 + tap8];
#pragma unroll
                    for (int wl = 0; wl < 2; wl++) {
                        ull tvv = tv[s][wl];
                        acc[wl][0][0] = fma2(tvv, w0.x, acc[wl][0][0]);
                        acc[wl][0][1] = fma2(tvv, w0.y, acc[wl][0][1]);
                        acc[wl][1][0] = fma2(tvv, w1.x, acc[wl][1][0]);
                        acc[wl][1][1] = fma2(tvv, w1.y, acc[wl][1][1]);
                        acc[wl][2][0] = fma2(tvv, w2.x, acc[wl][2][0]);
                        acc[wl][2][1] = fma2(tvv, w2.y, acc[wl][2][1]);
                        acc[wl][3][0] = fma2(tvv, w3.x, acc[wl][3][0]);
                        acc[wl][3][1] = fma2(tvv, w3.y, acc[wl][3][1]);
                    }
                }
            }
        }

        __syncthreads();   // prior epilogue done; safe to overwrite M
#pragma unroll
        for (int wl = 0; wl < 2; wl++)
#pragma unroll
            for (int so = 0; so < 4; so++)
#pragma unroll
                for (int br = 0; br < 2; br++)
                    *(ull*)(M + (wl*16 + tl)*136 + (so*2 + br)*16 + 2*uvp)
                        = acc[wl][so][br];
        __syncthreads();

        // ---- inverse + sigmoid + mask + so-reduction ----
        {
            const int so = tid & 3;
            const int t  = (tid >> 2) & 15;
            const int wl = tid >> 6;
            const int w1 = w1h*2 + wl;
            const int W1 = bw1*4 + w1;
            const int ti = B1*4 + (t >> 2);
            const int tj = B2*4 + (t & 3);
            const float* mc = M + (wl*16 + t)*136 + so*32;

            float p[4] = {0.f, 0.f, 0.f, 0.f};
#pragma unroll
            for (int br = 0; br < 2; br++) {
                float m[16];
#pragma unroll
                for (int u = 0; u < 16; u += 4) {
                    float4 mv = *(const float4*)(mc + br*16 + u);
                    m[u] = mv.x; m[u+1] = mv.y; m[u+2] = mv.z; m[u+3] = mv.w;
                }
                float p0[4], p1[4];
#pragma unroll
                for (int c = 0; c < 4; c++) {
                    p0[c] = m[c] + m[4+c] + m[8+c];
                    p1[c] = m[4+c] - m[8+c] - m[12+c];
                }
                p[0] += sigm(p0[0] + p0[1] + p0[2]);
                p[1] += sigm(p0[1] - p0[2] - p0[3]);
                p[2] += sigm(p1[0] + p1[1] + p1[2]);
                p[3] += sigm(p1[1] - p1[2] - p1[3]);
            }
            const float* xs = x + so*1048576 + (H1*32 + W1)*1024 + (2*ti)*32 + 2*tj;
            float2 x0 = *(const float2*)xs;
            float2 x1 = *(const float2*)(xs + 32);
            p[0] = (x0.x != 0.0f) ? p[0] : 0.0f;
            p[1] = (x0.y != 0.0f) ? p[1] : 0.0f;
            p[2] = (x1.x != 0.0f) ? p[2] : 0.0f;
            p[3] = (x1.y != 0.0f) ? p[3] : 0.0f;
#pragma unroll
            for (int k = 0; k < 4; k++) {
                p[k] += __shfl_xor_sync(0xFFFFFFFFu, p[k], 1);
                p[k] += __shfl_xor_sync(0xFFFFFFFFu, p[k], 2);
            }
            if (so == 0) {
                float* op = out + (H1*32 + W1)*1024 + (2*ti)*32 + 2*tj;
                *(float2*)op        = make_float2(p[0], p[1]);
                *(float2*)(op + 32) = make_float2(p[2], p[3]);
            }
        }
    }
}

extern "C" void kernel_launch(void* const* d_in, const int* in_sizes, int n_in,
                              void* d_out, int out_size) {
    const float* x    = (const float*)d_in[0];   // (1,2,2,32,32,32,32)
    const float* kern = (const float*)d_in[1];   // (729,)
    float* out = (float*)d_out;                  // (1,32,32,32,32)

    xform_kernel<<<4097, 256>>>(x, kern);
    conv_kernel<<<1024, 128, SMEM_BYTES>>>(x, out);
}

// round 17
// speedup vs baseline: 3.2138x; 1.0661x over previous
#include <cuda_runtime.h>
#include <cuda_bf16.h>

typedef unsigned long long ull;

// Zero-padded transform-domain input: [s 4][g1p 34][g2p 34][blk 16][in 16][uv 16]
// blk = (ti>>2)*4 + (tj>>2), in = (ti&3)*4 + (tj&3)  (4x4 tile-blocks,
// matching the conv CTA's B1/B2 tiling -> CTA reads are 1KB-contiguous).
// Borders (g1p=0,33 / g2p=0,33) are never written -> stay zero (static init).
__device__ float g_T[18939904];
// Weight pairs over uv: g_wp2[((ds*9+tap)*8 + uvp)*2 + br] = (U[2uvp], U[2uvp+1])
__device__ ull g_wp2[1296];

__device__ __forceinline__ ull pack2(float x, float y) {
    ull r; asm("mov.b64 %0, {%1, %2};" : "=l"(r) : "f"(x), "f"(y)); return r;
}
__device__ __forceinline__ ull fma2(ull a, ull b, ull c) {
    ull d; asm("fma.rn.f32x2 %0, %1, %2, %3;" : "=l"(d) : "l"(a), "l"(b), "l"(c)); return d;
}
__device__ __forceinline__ float sigm(float v) { return 1.0f / (1.0f + __expf(-v)); }

// ---------------------------------------------------------------------------
// Kernel 1: global input transform (+ weight prep in the extra block).
// ---------------------------------------------------------------------------
__global__ __launch_bounds__(256)
void xform_kernel(const float* __restrict__ x, const float* __restrict__ kern) {
    if (blockIdx.x == 4096) {
        // ---- weight prep: U = G g G^T per (branch, ds, tap) ----
        int i = threadIdx.x;
        if (i >= 162) return;
        int br = i / 81;
        int r  = i % 81;
        int ds = r / 9, tap = r % 9;
        int ds1 = ds / 3, ds2 = ds % 3;
        int dh1 = tap / 3, dw1 = tap % 3;
        float g[3][3];
        for (int a = 0; a < 3; a++)
            for (int b = 0; b < 3; b++) {
                int idx = (br == 0)
                    ? (((((ds1*3+ds2)*3+dh1)*3+dw1)*3+a)*3+b)
                    : (((((ds2*3+ds1)*3+a)*3+b)*3+dh1)*3+dw1);
                g[a][b] = kern[idx];
            }
        float t[4][3];
        for (int c = 0; c < 3; c++) {
            t[0][c] = g[0][c];
            t[1][c] = 0.5f*(g[0][c]+g[1][c]+g[2][c]);
            t[2][c] = 0.5f*(g[0][c]-g[1][c]+g[2][c]);
            t[3][c] = g[2][c];
        }
        for (int u = 0; u < 4; u++) {
            float U[4];
            U[0] = t[u][0];
            U[1] = 0.5f*(t[u][0]+t[u][1]+t[u][2]);
            U[2] = 0.5f*(t[u][0]-t[u][1]+t[u][2]);
            U[3] = t[u][2];
            for (int vp = 0; vp < 2; vp++) {
                int uvp = u*2 + vp;
                g_wp2[((ds*9+tap)*8 + uvp)*2 + br] = pack2(U[2*vp], U[2*vp+1]);
            }
        }
        return;
    }
    int gid = blockIdx.x * 256 + threadIdx.x;     // 0 .. 1048575
    int tt = gid & 255;
    int ti = tt >> 4, tj = tt & 15;
    int pg = gid >> 8;                            // s*1024 + g1*32 + g2
    int g2 = pg & 31, g1 = (pg >> 5) & 31, s = pg >> 10;
    const float* xs = x + pg * 1024;
    int h0 = 2*ti - 1, w0 = 2*tj - 1;
    float d[4][4];
#pragma unroll
    for (int r = 0; r < 4; r++) {
#pragma unroll
        for (int c = 0; c < 4; c++) {
            int h = h0 + r, w = w0 + c;
            float v = 0.0f;
            if (((unsigned)h < 32u) && ((unsigned)w < 32u))
                v = fmaxf(xs[h*32 + w], 0.0f);
            d[r][c] = v;
        }
    }
    float tr[4][4];
#pragma unroll
    for (int c = 0; c < 4; c++) {
        tr[0][c] = d[0][c] - d[2][c];
        tr[1][c] = d[1][c] + d[2][c];
        tr[2][c] = d[2][c] - d[1][c];
        tr[3][c] = d[1][c] - d[3][c];
    }
    // blocked tile index: 4x4 blocks of 4x4 tiles
    int pos = ((ti >> 2) * 4 + (tj >> 2)) * 16 + (ti & 3) * 4 + (tj & 3);
    float* o = g_T + ((((long)s*34 + (g1+1))*34 + (g2+1))*256 + pos)*16;
#pragma unroll
    for (int u = 0; u < 4; u++) {
        float V0 = tr[u][0] - tr[u][2];
        float V1 = tr[u][1] + tr[u][2];
        float V2 = tr[u][2] - tr[u][1];
        float V3 = tr[u][1] - tr[u][3];
        *(float4*)(o + u*4) = make_float4(V0, V1, V2, V3);
    }
}

// ---------------------------------------------------------------------------
// Kernel 2 (R12-proven hot loop + blocked-contiguous T layout).
// CTA: (h1,w1) 4x4 region x 4x4 tile-block (8x8 h2w2) = 1024 outputs.
// 128 threads = tile-local tl(16) x uvp(8). 8 phases of (h1, w1-half).
// Tap-outer loop: 8 unconditional T-LDG.64 per tap (compiler-batched MLP);
// warp-contiguous 256B spans -> 2 L1 wavefronts per LDG (was 4).
// SMEM: Wsm 1296 ull (10368 B) + M [2][16][136] fl (17408 B) = 27776 B.
// ---------------------------------------------------------------------------
#define SMEM_BYTES 27776
#define TS_S   4734976L   // 34*34*4096 floats
#define TS_G1  139264L    // 34*4096
#define TS_G2  4096L      // 256*16

__global__ __launch_bounds__(128, 6)
void conv_kernel(const float* __restrict__ x, float* __restrict__ out) {
    extern __shared__ float sm[];
    ull* Wsm = (ull*)sm;
    float* M = sm + 2592;

    const int tid = threadIdx.x;
    const int bid = blockIdx.x;
    const int B2  = bid & 3;
    const int B1  = (bid >> 2) & 3;
    const int bw1 = (bid >> 4) & 7;
    const int bh1 = bid >> 7;

    {   // vectorized weight copy (648 x 16B)
        ulonglong2* Wd = (ulonglong2*)Wsm;
        const ulonglong2* Ws = (const ulonglong2*)g_wp2;
        for (int i = tid; i < 648; i += 128) Wd[i] = Ws[i];
    }

    const int uvp = tid & 7;
    const int tl  = tid >> 3;
    const int ta  = tl >> 2, tb = tl & 3;
    // blocked layout: CTA's 16 tiles are contiguous at blk = B1*4+B2
    const long toff = (((B1*4 + B2)*16 + tl)*16) + 2*uvp;
    const ulonglong2* Wq = (const ulonglong2*)Wsm;
    __syncthreads();

#pragma unroll 1
    for (int qb = 0; qb < 8; qb++) {
        const int h1  = qb >> 1;
        const int w1h = qb & 1;
        const int H1  = bh1*4 + h1;
        const int g2p0 = bw1*4 + w1h*2;      // padded g2 base

        // Per-s_in T base pointers (padded layout: no bounds checks anywhere)
        const float* Tb0 = g_T + ((0*34 + H1)*34 + g2p0)*TS_G2 + toff;
        const float* Tb1 = Tb0 + TS_S;
        const float* Tb2 = Tb1 + TS_S;
        const float* Tb3 = Tb2 + TS_S;

        ull acc[2][4][2];
#pragma unroll
        for (int wl = 0; wl < 2; wl++)
#pragma unroll
            for (int so = 0; so < 4; so++) { acc[wl][so][0] = 0ull; acc[wl][so][1] = 0ull; }

#pragma unroll
        for (int dh1 = 0; dh1 < 3; dh1++) {
#pragma unroll
            for (int dw1 = 0; dw1 < 3; dw1++) {
                // ---- 8 independent T loads (immediate offsets) ----
                ull tv[4][2];
#pragma unroll
                for (int wl = 0; wl < 2; wl++) {
                    const long o = dh1*TS_G1 + (dw1+wl)*TS_G2;
                    tv[0][wl] = *(const ull*)(Tb0 + o);
                    tv[1][wl] = *(const ull*)(Tb1 + o);
                    tv[2][wl] = *(const ull*)(Tb2 + o);
                    tv[3][wl] = *(const ull*)(Tb3 + o);
                }
                const int tap8 = (dh1*3 + dw1) * 8;
#pragma unroll
                for (int s = 0; s < 4; s++) {
                    const int s1i = s >> 1, s2i = s & 1;
                    // ds(s,so)*72 folds to a compile-time constant per (s,so)
                    ulonglong2 w0 = Wq[uvp + ((s1i+1)*3 + s2i+1)*72 + tap8];
                    ulonglong2 w1 = Wq[uvp + ((s1i+1)*3 + s2i  )*72 + tap8];
                    ulonglong2 w2 = Wq[uvp + (( s1i )*3 + s2i+1)*72 + tap8];
                    ulonglong2 w3 = Wq[uvp + (( s1i )*3 + s2i  )*72 + tap8];
#pragma unroll
                    for (int wl = 0; wl < 2; wl++) {
                        ull tvv = tv[s][wl];
                        acc[wl][0][0] = fma2(tvv, w0.x, acc[wl][0][0]);
                        acc[wl][0][1] = fma2(tvv, w0.y, acc[wl][0][1]);
                        acc[wl][1][0] = fma2(tvv, w1.x, acc[wl][1][0]);
                        acc[wl][1][1] = fma2(tvv, w1.y, acc[wl][1][1]);
                        acc[wl][2][0] = fma2(tvv, w2.x, acc[wl][2][0]);
                        acc[wl][2][1] = fma2(tvv, w2.y, acc[wl][2][1]);
                        acc[wl][3][0] = fma2(tvv, w3.x, acc[wl][3][0]);
                        acc[wl][3][1] = fma2(tvv, w3.y, acc[wl][3][1]);
                    }
                }
            }
        }

        __syncthreads();   // prior epilogue done; safe to overwrite M
#pragma unroll
        for (int wl = 0; wl < 2; wl++)
#pragma unroll
            for (int so = 0; so < 4; so++)
#pragma unroll
                for (int br = 0; br < 2; br++)
                    *(ull*)(M + (wl*16 + tl)*136 + (so*2 + br)*16 + 2*uvp)
                        = acc[wl][so][br];
        __syncthreads();

        // ---- inverse + sigmoid + mask + so-reduction ----
        {
            const int so = tid & 3;
            const int t  = (tid >> 2) & 15;
            const int wl = tid >> 6;
            const int w1 = w1h*2 + wl;
            const int W1 = bw1*4 + w1;
            const int ti = B1*4 + (t >> 2);
            const int tj = B2*4 + (t & 3);
            const float* mc = M + (wl*16 + t)*136 + so*32;

            float p[4] = {0.f, 0.f, 0.f, 0.f};
#pragma unroll
            for (int br = 0; br < 2; br++) {
                float m[16];
#pragma unroll
                for (int u = 0; u < 16; u += 4) {
                    float4 mv = *(const float4*)(mc + br*16 + u);
                    m[u] = mv.x; m[u+1] = mv.y; m[u+2] = mv.z; m[u+3] = mv.w;
                }
                float p0[4], p1[4];
#pragma unroll
                for (int c = 0; c < 4; c++) {
                    p0[c] = m[c] + m[4+c] + m[8+c];
                    p1[c] = m[4+c] - m[8+c] - m[12+c];
                }
                p[0] += sigm(p0[0] + p0[1] + p0[2]);
                p[1] += sigm(p0[1] - p0[2] - p0[3]);
                p[2] += sigm(p1[0] + p1[1] + p1[2]);
                p[3] += sigm(p1[1] - p1[2] - p1[3]);
            }
            const float* xs = x + so*1048576 + (H1*32 + W1)*1024 + (2*ti)*32 + 2*tj;
            float2 x0 = *(const float2*)xs;
            float2 x1 = *(const float2*)(xs + 32);
            p[0] = (x0.x != 0.0f) ? p[0] : 0.0f;
            p[1] = (x0.y != 0.0f) ? p[1] : 0.0f;
            p[2] = (x1.x != 0.0f) ? p[2] : 0.0f;
            p[3] = (x1.y != 0.0f) ? p[3] : 0.0f;
#pragma unroll
            for (int k = 0; k < 4; k++) {
                p[k] += __shfl_xor_sync(0xFFFFFFFFu, p[k], 1);
                p[k] += __shfl_xor_sync(0xFFFFFFFFu, p[k], 2);
            }
            if (so == 0) {
                float* op = out + (H1*32 + W1)*1024 + (2*ti)*32 + 2*tj;
                *(float2*)op        = make_float2(p[0], p[1]);
                *(float2*)(op + 32) = make_float2(p[2], p[3]);
            }
        }
    }
}

extern "C" void kernel_launch(void* const* d_in, const int* in_sizes, int n_in,
                              void* d_out, int out_size) {
    const float* x    = (const float*)d_in[0];   // (1,2,2,32,32,32,32)
    const float* kern = (const float*)d_in[1];   // (729,)
    float* out = (float*)d_out;                  // (1,32,32,32,32)

    xform_kernel<<<4097, 256>>>(x, kern);
    conv_kernel<<<1024, 128, SMEM_BYTES>>>(x, out);
}